// round 5
// baseline (speedup 1.0000x reference)
#include <cuda_runtime.h>
#include <cuda_bf16.h>
#include <stdint.h>

// out[m] = x[m]·W + b + 0.5*||x[m]V||^2 - 0.5*(sum_i x[m,i])^2 * ||V.sum(0)||^2
// x: (16384,4096) f32, W: (1,4096) f32, b: (1,) f32, V: (4096,128) f32, out f32.

#define MROWS 16384
#define KDIM  4096
#define NDIM  128
#define KC    64                     // K per chunk (128B bf16 per row)
#define NCH   (KDIM / KC)            // 64
#define TILEB 16384                  // 128 rows x 128B

// dynamic smem: A[2] | B[2] | red | sxs | sws
#define OF_B   (2 * TILEB)
#define OF_RED (4 * TILEB)
#define OF_SXS (OF_RED + 1024)
#define OF_SWS (OF_SXS + 512)
#define SMEM_TOTAL (OF_SWS + 512)    // 67584

__device__ __nv_bfloat16 g_Vt[(size_t)NCH * NDIM * KC];  // chunk-major [c][n][kk]
__device__ float g_spart[64 * NDIM];
__device__ float g_s2;

// ---------------- helpers ----------------

static __device__ __forceinline__ uint32_t smem_u32(const void* p) {
    uint32_t r;
    asm("{ .reg .u64 t; cvta.to.shared.u64 t, %1; cvt.u32.u64 %0, t; }"
        : "=r"(r) : "l"(p));
    return r;
}

static __device__ __forceinline__ uint32_t pack2(float lo, float hi) {
    __nv_bfloat162 h = __float22bfloat162_rn(make_float2(lo, hi));
    return *reinterpret_cast<uint32_t*>(&h);
}

#define MMA_OP(d, a0, a1, a2, a3, b0, b1)                                  \
    asm volatile(                                                          \
        "mma.sync.aligned.m16n8k16.row.col.f32.bf16.bf16.f32 "             \
        "{%0,%1,%2,%3}, {%4,%5,%6,%7}, {%8,%9}, {%0,%1,%2,%3};"            \
        : "+f"((d)[0]), "+f"((d)[1]), "+f"((d)[2]), "+f"((d)[3])           \
        : "r"(a0), "r"(a1), "r"(a2), "r"(a3), "r"(b0), "r"(b1))

#define LDSM_X4(r0, r1, r2, r3, addr)                                      \
    asm volatile("ldmatrix.sync.aligned.m8n8.x4.shared.b16 "               \
                 "{%0,%1,%2,%3}, [%4];"                                    \
                 : "=r"(r0), "=r"(r1), "=r"(r2), "=r"(r3) : "r"(addr))

#define BAR_SYNC(id)   asm volatile("bar.sync %0, 384;"   :: "r"(id) : "memory")
#define BAR_ARRIVE(id) asm volatile("bar.arrive %0, 384;" :: "r"(id) : "memory")

// ---------------- prep kernels ----------------

__global__ void prep_kernel(const float* __restrict__ V) {
    __shared__ __align__(16) __nv_bfloat16 sm[128 * 66];
    __shared__ float ps[256];
    const int t = threadIdx.x;
    const int b = blockIdx.x;
    const int k0 = b * 64;
    const int n = t & 127;
    const int half = t >> 7;

    float partial = 0.f;
#pragma unroll
    for (int i = 0; i < 32; i++) {
        int kk = 2 * i + half;
        float v = V[(size_t)(k0 + kk) * NDIM + n];
        partial += v;
        sm[n * 66 + kk] = __float2bfloat16(v);
    }
    ps[t] = partial;
    __syncthreads();
    if (t < 128) g_spart[b * 128 + t] = ps[t] + ps[t + 128];

    const int r = t >> 1, part = t & 1;
    const uint32_t* src = (const uint32_t*)((const char*)sm + r * 132 + part * 64);
    uint32_t v0[16];
#pragma unroll
    for (int i = 0; i < 16; i++) v0[i] = src[i];
    uint4* dst = (uint4*)((char*)g_Vt + (size_t)b * 16384 + (size_t)r * 128 + part * 64);
#pragma unroll
    for (int i = 0; i < 4; i++)
        dst[i] = make_uint4(v0[4*i], v0[4*i+1], v0[4*i+2], v0[4*i+3]);
}

__global__ void s2_kernel() {
    __shared__ float sh[128];
    int t = threadIdx.x;
    float s = 0.f;
    for (int b2 = 0; b2 < 64; b2++) s += g_spart[b2 * 128 + t];
    sh[t] = s * s;
    __syncthreads();
    for (int o = 64; o > 0; o >>= 1) {
        if (t < o) sh[t] += sh[t + o];
        __syncthreads();
    }
    if (t == 0) g_s2 = sh[0];
}

// ---------------- main kernel ----------------
// 384 thr: warps 0-7 consumers (LDSM+HMMA), warps 8-11 producers
// (LDG x + V^T, fp32 side sums, bf16 cvt, swizzled STS).
// Named barriers: 1/2 = produced(buf0/1), 3/4 = consumed(buf0/1).

__global__ void __launch_bounds__(384, 1) fm_main(
    const float* __restrict__ x, const float* __restrict__ W,
    const float* __restrict__ bias, float* __restrict__ out)
{
    extern __shared__ __align__(16) char smem[];
    float (*red)[2] = (float(*)[2])(smem + OF_RED);
    float* sxs = (float*)(smem + OF_SXS);
    float* sws = (float*)(smem + OF_SWS);

    const int t = threadIdx.x;
    const int wid = t >> 5, lane = t & 31;
    const int mbase = blockIdx.x * 128;
    const uint32_t sb = smem_u32(smem);

    if (t < 256) {
        // ================= CONSUMERS =================
        const int mstrip = wid & 3;
        const int nhalf  = wid >> 2;

        // A ldmatrix lane constants (rows = lane&15, khalf = lane>>4)
        const int row_a = mstrip * 32 + (lane & 15);
        const uint32_t a_rb = sb + (uint32_t)row_a * 128;
        const uint32_t xra = (uint32_t)(row_a & 7);
        const uint32_t kha = (uint32_t)(lane >> 4);
        // B: rows = nhalf*64 + (lane>>4)*8 + (lane&7), khalf = (lane>>3)&1
        const int row_b = nhalf * 64 + (lane >> 4) * 8 + (lane & 7);
        const uint32_t b_rb = sb + OF_B + (uint32_t)row_b * 128;
        const uint32_t xrb = (uint32_t)(lane & 7);
        const uint32_t khb = (uint32_t)((lane >> 3) & 1);

        float acc[2][8][4];
#pragma unroll
        for (int i = 0; i < 2; i++)
#pragma unroll
            for (int j = 0; j < 8; j++)
#pragma unroll
                for (int k = 0; k < 4; k++) acc[i][j][k] = 0.f;

#pragma unroll 1
        for (int c = 0; c < NCH; c++) {
            const int buf = c & 1;
            BAR_SYNC(1 + buf);
            const uint32_t ao = (uint32_t)buf * TILEB;
#pragma unroll
            for (int ks = 0; ks < 4; ks++) {
                const uint32_t offA = (((2u * ks + kha) ^ xra) << 4);
                uint32_t afr[2][4];
                LDSM_X4(afr[0][0], afr[0][1], afr[0][2], afr[0][3],
                        a_rb + ao + offA);
                LDSM_X4(afr[1][0], afr[1][1], afr[1][2], afr[1][3],
                        a_rb + ao + offA + 2048);
                const uint32_t offB = (((2u * ks + khb) ^ xrb) << 4);
                uint32_t bfr[8][2];
#pragma unroll
                for (int p = 0; p < 4; p++)
                    LDSM_X4(bfr[2*p][0], bfr[2*p][1], bfr[2*p+1][0], bfr[2*p+1][1],
                            b_rb + ao + offB + p * 2048);
#pragma unroll
                for (int mt = 0; mt < 2; mt++)
#pragma unroll
                    for (int nt = 0; nt < 8; nt++)
                        MMA_OP(acc[mt][nt], afr[mt][0], afr[mt][1],
                               afr[mt][2], afr[mt][3], bfr[nt][0], bfr[nt][1]);
            }
            BAR_ARRIVE(3 + buf);
        }

        // epilogue: term1 partials
#pragma unroll
        for (int mt = 0; mt < 2; mt++) {
            float p0 = 0.f, p1 = 0.f;
#pragma unroll
            for (int nt = 0; nt < 8; nt++) {
                p0 += acc[mt][nt][0] * acc[mt][nt][0] + acc[mt][nt][1] * acc[mt][nt][1];
                p1 += acc[mt][nt][2] * acc[mt][nt][2] + acc[mt][nt][3] * acc[mt][nt][3];
            }
            p0 += __shfl_xor_sync(0xffffffffu, p0, 1);
            p0 += __shfl_xor_sync(0xffffffffu, p0, 2);
            p1 += __shfl_xor_sync(0xffffffffu, p1, 1);
            p1 += __shfl_xor_sync(0xffffffffu, p1, 2);
            if ((lane & 3) == 0) {
                red[mstrip * 32 + mt * 16 + (lane >> 2)][nhalf]     = p0;
                red[mstrip * 32 + mt * 16 + 8 + (lane >> 2)][nhalf] = p1;
            }
        }
    } else {
        // ================= PRODUCERS =================
        const int pp = t - 256;        // 0..127
        const int pw = pp >> 3;        // 0..15 (row-in-16 group)
        const int pj = pp & 7;         // 16B slot
        const uint32_t rlow = (uint32_t)(pw & 7);

        // A gmem: rows 16i+pw; thread covers bytes [pj*16, +16) and [128+pj*16, +16)
        const char* xb = (const char*)x + ((size_t)(mbase + pw) << 14) + pj * 16;
        // B gmem: chunk-major, 16B units pp + 128*i
        const char* vb = (const char*)g_Vt + (size_t)pp * 16;
        const char* wb = (const char*)W + pj * 16;

        // STS offsets (XOR-16B swizzle within 128B rows)
        const uint32_t s0 = (uint32_t)(pj >> 1);
        const uint32_t o8 = (uint32_t)(pj & 1) * 8;
        const uint32_t aoff0 = sb + ((s0 ^ rlow) << 4) + o8 + pw * 128;
        const uint32_t aoff1 = sb + (((s0 + 4) ^ rlow) << 4) + o8 + pw * 128;
        const uint32_t boff  = sb + OF_B + (((uint32_t)pj ^ rlow) << 4) + pw * 128;

        float sx[8], sw[8];
#pragma unroll
        for (int i = 0; i < 8; i++) { sx[i] = 0.f; sw[i] = 0.f; }

        uint2 ap0[8], ap1[8];
        uint4 bp[8];

#define LOAD_PACK(c) do {                                                   \
        const float4 wlo = *(const float4*)(wb + (size_t)(c) * 256);        \
        const float4 whi = *(const float4*)(wb + (size_t)(c) * 256 + 128);  \
        _Pragma("unroll")                                                   \
        for (int i = 0; i < 8; i++) {                                       \
            const char* xr_ = xb + (size_t)i * 262144 + (size_t)(c) * 256;  \
            const float4 q0 = *(const float4*)(xr_);                        \
            const float4 q1 = *(const float4*)(xr_ + 128);                  \
            bp[i] = *(const uint4*)(vb + (size_t)(c) * 16384 + i * 2048);   \
            sx[i] += (q0.x + q0.y) + (q0.z + q0.w)                          \
                   + (q1.x + q1.y) + (q1.z + q1.w);                         \
            sw[i] += q0.x * wlo.x + q0.y * wlo.y + q0.z * wlo.z + q0.w * wlo.w \
                   + q1.x * whi.x + q1.y * whi.y + q1.z * whi.z + q1.w * whi.w; \
            ap0[i] = make_uint2(pack2(q0.x, q0.y), pack2(q0.z, q0.w));      \
            ap1[i] = make_uint2(pack2(q1.x, q1.y), pack2(q1.z, q1.w));      \
        }                                                                   \
    } while (0)

#define STS_BUF(buf) do {                                                   \
        const uint32_t bo_ = (uint32_t)(buf) * TILEB;                       \
        _Pragma("unroll")                                                   \
        for (int i = 0; i < 8; i++) {                                       \
            asm volatile("st.shared.v2.b32 [%0], {%1,%2};"                  \
                         :: "r"(aoff0 + bo_ + i * 2048),                    \
                            "r"(ap0[i].x), "r"(ap0[i].y));                  \
            asm volatile("st.shared.v2.b32 [%0], {%1,%2};"                  \
                         :: "r"(aoff1 + bo_ + i * 2048),                    \
                            "r"(ap1[i].x), "r"(ap1[i].y));                  \
            asm volatile("st.shared.v4.b32 [%0], {%1,%2,%3,%4};"            \
                         :: "r"(boff + bo_ + i * 2048), "r"(bp[i].x),       \
                            "r"(bp[i].y), "r"(bp[i].z), "r"(bp[i].w));      \
        }                                                                   \
    } while (0)

        LOAD_PACK(0);
#pragma unroll 1
        for (int c = 0; c < NCH; c++) {
            const int buf = c & 1;
            if (c >= 2) BAR_SYNC(3 + buf);
            STS_BUF(buf);
            BAR_ARRIVE(1 + buf);
            if (c < NCH - 1) LOAD_PACK(c + 1);
        }

        // reduce side sums over the 8 threads sharing each row set
#pragma unroll
        for (int i = 0; i < 8; i++) {
#pragma unroll
            for (int o = 4; o > 0; o >>= 1) {
                sx[i] += __shfl_xor_sync(0xffffffffu, sx[i], o);
                sw[i] += __shfl_xor_sync(0xffffffffu, sw[i], o);
            }
        }
        if (pj == 0) {
#pragma unroll
            for (int i = 0; i < 8; i++) {
                sxs[i * 16 + pw] = sx[i];
                sws[i * 16 + pw] = sw[i];
            }
        }
    }

    __syncthreads();

    if (t < 128) {
        const float t1 = red[t][0] + red[t][1];
        const float s_ = sxs[t];
        out[mbase + t] = sws[t] + bias[0] + 0.5f * t1 - 0.5f * s_ * s_ * g_s2;
    }
}

// ---------------- launch ----------------

extern "C" void kernel_launch(void* const* d_in, const int* in_sizes, int n_in,
                              void* d_out, int out_size) {
    (void)in_sizes; (void)n_in; (void)out_size;
    const float* x = (const float*)d_in[0];
    const float* W = (const float*)d_in[1];
    const float* b = (const float*)d_in[2];
    const float* V = (const float*)d_in[3];
    float* out = (float*)d_out;

    cudaFuncSetAttribute(fm_main, cudaFuncAttributeMaxDynamicSharedMemorySize, SMEM_TOTAL);

    prep_kernel<<<64, 256>>>(V);
    s2_kernel<<<1, 128>>>();
    fm_main<<<MROWS / 128, 384, SMEM_TOTAL>>>(x, W, b, out);
}